// round 5
// baseline (speedup 1.0000x reference)
#include <cuda_runtime.h>
#include <cstdint>

#define B_ 2
#define T_ 2048
#define S_ 2048
#define E_ 1024
#define H_ 16
#define D_ 64
#define M_ (B_*T_)

// Scratch (device globals; no allocation allowed)
__device__ float g_q[B_*H_*T_*D_];
__device__ float g_k[B_*H_*S_*D_];
__device__ float g_v[B_*H_*S_*D_];
__device__ float g_attn[M_*E_];

// ---------------------------------------------------------------------------
// helpers
// ---------------------------------------------------------------------------
__device__ __forceinline__ uint32_t f2tf(float x) {
    uint32_t r;
    asm("cvt.rna.tf32.f32 %0, %1;" : "=r"(r) : "f"(x));
    return r;
}

__device__ __forceinline__ void mma_tf32(float c[4],
                                         uint32_t a0, uint32_t a1, uint32_t a2, uint32_t a3,
                                         uint32_t b0, uint32_t b1) {
    asm("mma.sync.aligned.m16n8k8.row.col.f32.tf32.tf32.f32 "
        "{%0,%1,%2,%3},{%4,%5,%6,%7},{%8,%9},{%0,%1,%2,%3};"
        : "+f"(c[0]), "+f"(c[1]), "+f"(c[2]), "+f"(c[3])
        : "r"(a0), "r"(a1), "r"(a2), "r"(a3), "r"(b0), "r"(b1));
}

__device__ __forceinline__ void cp16(void* smem_dst, const void* gmem_src) {
    uint32_t s = (uint32_t)__cvta_generic_to_shared(smem_dst);
    asm volatile("cp.async.cg.shared.global [%0], [%1], 16;" :: "r"(s), "l"(gmem_src));
}
__device__ __forceinline__ void cp_commit() {
    asm volatile("cp.async.commit_group;");
}
__device__ __forceinline__ void cp_wait0() {
    asm volatile("cp.async.wait_group 0;");
}
__device__ __forceinline__ void cp_wait1() {
    asm volatile("cp.async.wait_group 1;");
}

// ---------------------------------------------------------------------------
// GEMM (tf32 tensor, cp.async double-buffered):
// out[m][n] = sum_k A[m][k]*W[n][k] + bias[n]
// ---------------------------------------------------------------------------
#define GEMM_SMEM_FLOATS (2*(256*36) + 2*(64*36))
#define GEMM_SMEM_BYTES  (GEMM_SMEM_FLOATS * 4)

__global__ void __launch_bounds__(256, 2) gemm_tc(
    const float* __restrict__ A, const float* __restrict__ W,
    const float* __restrict__ bias, float* __restrict__ out, int headMajor)
{
    extern __shared__ float gsm[];
    float* As = gsm;                 // [2][256][36]
    float* Ws = gsm + 2 * 256 * 36;  // [2][64][36]

    const int tid  = threadIdx.x;
    const int lane = tid & 31;
    const int wid  = tid >> 5;
    const int m0   = blockIdx.y * 256;
    const int n0   = blockIdx.x * 64;
    const int qg   = lane >> 2;
    const int qt   = lane & 3;

    float acc[2][8][4];
#pragma unroll
    for (int mt = 0; mt < 2; mt++)
#pragma unroll
        for (int j = 0; j < 8; j++)
#pragma unroll
            for (int i = 0; i < 4; i++) acc[mt][j][i] = 0.f;

    const float* Arow = A + (size_t)(m0 + tid) * E_;
    const float* Wrow = W + (size_t)(n0 + (tid >> 2)) * E_ + (tid & 3) * 8;
    float* Asr = As + tid * 36;
    float* Wsr = Ws + (tid >> 2) * 36 + (tid & 3) * 8;

#pragma unroll
    for (int i = 0; i < 8; i++) cp16(Asr + i * 4, Arow + i * 4);
#pragma unroll
    for (int i = 0; i < 2; i++) cp16(Wsr + i * 4, Wrow + i * 4);
    cp_commit();

    const int NSTEP = E_ / 32;
    for (int s = 0; s < NSTEP; s++) {
        const int buf  = s & 1;
        const int nbuf = buf ^ 1;
        if (s + 1 < NSTEP) {
            const int kt = (s + 1) * 32;
#pragma unroll
            for (int i = 0; i < 8; i++)
                cp16(Asr + nbuf * 256 * 36 + i * 4, Arow + kt + i * 4);
#pragma unroll
            for (int i = 0; i < 2; i++)
                cp16(Wsr + nbuf * 64 * 36 + i * 4, Wrow + kt + i * 4);
            cp_commit();
            cp_wait1();
        } else {
            cp_wait0();
        }
        __syncthreads();

        const float* Ab = As + buf * 256 * 36;
        const float* Wb = Ws + buf * 64 * 36;
#pragma unroll
        for (int kk = 0; kk < 4; kk++) {
            uint32_t a[2][4];
#pragma unroll
            for (int mt = 0; mt < 2; mt++) {
                const int ar = wid * 32 + mt * 16 + qg;
                const int ac = kk * 8 + qt;
                a[mt][0] = f2tf(Ab[ar * 36 + ac]);
                a[mt][1] = f2tf(Ab[(ar + 8) * 36 + ac]);
                a[mt][2] = f2tf(Ab[ar * 36 + ac + 4]);
                a[mt][3] = f2tf(Ab[(ar + 8) * 36 + ac + 4]);
            }
#pragma unroll
            for (int j = 0; j < 8; j++) {
                const int br = j * 8 + qg;
                const int bc = kk * 8 + qt;
                uint32_t b0 = f2tf(Wb[br * 36 + bc]);
                uint32_t b1 = f2tf(Wb[br * 36 + bc + 4]);
                mma_tf32(acc[0][j], a[0][0], a[0][1], a[0][2], a[0][3], b0, b1);
                mma_tf32(acc[1][j], a[1][0], a[1][1], a[1][2], a[1][3], b0, b1);
            }
        }
        __syncthreads();
    }

#pragma unroll
    for (int mt = 0; mt < 2; mt++) {
        const int row0 = m0 + wid * 32 + mt * 16 + qg;
#pragma unroll
        for (int j = 0; j < 8; j++) {
            const int col = n0 + j * 8 + 2 * qt;
            const float bz0 = bias[col], bz1 = bias[col + 1];
            float v00 = acc[mt][j][0] + bz0, v01 = acc[mt][j][1] + bz1;
            float v10 = acc[mt][j][2] + bz0, v11 = acc[mt][j][3] + bz1;
            if (headMajor) {
                const int h = col >> 6, d = col & 63;
                {
                    const int b = row0 >> 11, t = row0 & 2047;
                    float2 o = {v00, v01};
                    *(float2*)&out[(size_t)((b * H_ + h) * T_ + t) * D_ + d] = o;
                }
                {
                    const int r1 = row0 + 8;
                    const int b = r1 >> 11, t = r1 & 2047;
                    float2 o = {v10, v11};
                    *(float2*)&out[(size_t)((b * H_ + h) * T_ + t) * D_ + d] = o;
                }
            } else {
                float2 o0 = {v00, v01};
                float2 o1 = {v10, v11};
                *(float2*)&out[(size_t)row0 * E_ + col] = o0;
                *(float2*)&out[(size_t)(row0 + 8) * E_ + col] = o1;
            }
        }
    }
}

// ---------------------------------------------------------------------------
// Flash attention, tf32 tensor cores, fragment-pair smem layouts.
// Grid (T/128, H, B), 256 threads = 8 warps; warp owns 16 full q-rows.
// All smem operands pre-converted to tf32; K/V register-pipelined.
// ---------------------------------------------------------------------------
#define QSTR 36   // uint4 entries per (wid,qg) row: 32 used + 4 pad
#define KSTR 36   // uint2 entries per K row:        32 used + 4 pad
#define VSTR 68   // uint2 entries per V pair-row:   64 used + 4 pad
// offsets in u32 words:
#define AQ_OFF 0
#define AK_OFF (64*QSTR*4)             // 9216
#define AV_OFF (AK_OFF + 64*KSTR*2)    // 13824
#define AP_OFF (AV_OFF + 32*VSTR*2)    // 18176
#define AM_OFF (AP_OFF + 8*512*2)      // 26368
#define ATTN_SMEM_U32 (AM_OFF + 64)
#define ATTN_SMEM_BYTES (ATTN_SMEM_U32 * 4)

__global__ void __launch_bounds__(256, 2) attn_tc(
    const float* __restrict__ spatial, const float* __restrict__ dirb,
    const float* __restrict__ amask, const unsigned char* __restrict__ pmask,
    float* __restrict__ outp)
{
    extern __shared__ uint32_t smu[];
    float* Ms = (float*)(smu + AM_OFF);

    const int tid  = threadIdx.x;
    const int lane = tid & 31;
    const int wid  = tid >> 5;
    const int qg   = lane >> 2;
    const int qt   = lane & 3;
    const int t0   = blockIdx.x * 128;
    const int h    = blockIdx.y;
    const int b    = blockIdx.z;
    const int r0   = wid * 16;

    const float* qbase = g_q + (size_t)((b * H_ + h) * T_ + t0) * D_;
    const float* kbase = g_k + (size_t)(b * H_ + h) * S_ * D_;
    const float* vbase = g_v + (size_t)(b * H_ + h) * S_ * D_;

    // ---- stage Q once, directly in uint4 fragment layout ----
    {
        const int wq = tid >> 5, qgq = (tid >> 2) & 7, qtq = tid & 3;
        const float* q0 = qbase + (16 * wq + qgq) * D_;
        const float* q1 = q0 + 8 * D_;
#pragma unroll
        for (int kk = 0; kk < 8; kk++) {
            const int c = kk * 8 + qtq;
            uint4 u = {f2tf(q0[c]), f2tf(q1[c]), f2tf(q0[c + 4]), f2tf(q1[c + 4])};
            *(uint4*)&smu[AQ_OFF + ((wq * 8 + qgq) * QSTR + kk * 4 + qtq) * 4] = u;
        }
    }

    // K/V register pipeline: thread roles
    const int rK  = tid >> 2;          // K row 0..63
    const int c0K = (tid & 3) * 16;    // K col base
    const int pV  = tid >> 3;          // V pair-row 0..31
    const int rV  = (pV >> 2) * 8 + (pV & 3);
    const int c0V = (tid & 7) * 8;     // V col base

    float kf[16], vf[16];
    // prologue: load tile 0
    {
        const float* ks = kbase + (size_t)rK * D_ + c0K;
#pragma unroll
        for (int i = 0; i < 4; i++) *(float4*)&kf[i * 4] = *(const float4*)(ks + i * 4);
        const float* v0 = vbase + (size_t)rV * D_ + c0V;
        const float* v1 = vbase + (size_t)(rV + 4) * D_ + c0V;
        *(float4*)&vf[0]  = *(const float4*)(v0);
        *(float4*)&vf[4]  = *(const float4*)(v0 + 4);
        *(float4*)&vf[8]  = *(const float4*)(v1);
        *(float4*)&vf[12] = *(const float4*)(v1 + 4);
    }

    float mrow[2] = {-1e30f, -1e30f};
    float lrow[2] = {0.f, 0.f};
    float oacc[8][4];
#pragma unroll
    for (int j = 0; j < 8; j++)
#pragma unroll
        for (int i = 0; i < 4; i++) oacc[j][i] = 0.f;

    const int ra = t0 + r0 + qg;
    const int rb = ra + 8;
    const size_t bh = (size_t)(b * H_ + h) * T_;
    const float* spA = spatial + (bh + ra) * S_;
    const float* spB = spatial + (bh + rb) * S_;
    const float* dbA = dirb + (bh + ra) * S_;
    const float* dbB = dirb + (bh + rb) * S_;
    const float* amA = amask + (size_t)ra * S_;
    const float* amB = amask + (size_t)rb * S_;

    const int pwoff = AP_OFF + wid * 1024;  // per-warp P region (512 uint2)

    for (int s0 = 0; s0 < S_; s0 += 64) {
        __syncthreads();   // all warps done reading Kp/Vp/Pp of prior tile

        // ---- STS K pairs (K[s][d], K[s][d+4]) as tf32 ----
#pragma unroll
        for (int g = 0; g < 2; g++) {
            const int pbase = rK * KSTR + ((c0K >> 3) + g) * 4;
#pragma unroll
            for (int m = 0; m < 4; m++) {
                uint2 pr = {f2tf(kf[g * 8 + m]), f2tf(kf[g * 8 + m + 4])};
                *(uint2*)&smu[AK_OFF + (pbase + m) * 2] = pr;
            }
        }
        // ---- STS V row-pairs (V[s][d], V[s+4][d]) as tf32 ----
#pragma unroll
        for (int c = 0; c < 8; c += 2) {
            uint4 u = {f2tf(vf[c]), f2tf(vf[8 + c]), f2tf(vf[c + 1]), f2tf(vf[8 + c + 1])};
            *(uint4*)&smu[AV_OFF + (pV * VSTR + c0V + c) * 2] = u;
        }
        if (tid < 64)
            Ms[tid] = pmask[b * S_ + s0 + tid] ? -1e30f : 0.f;
        __syncthreads();

        // ---- QK^T: S[16 x 64] per warp ----
        float sacc[8][4];
#pragma unroll
        for (int j = 0; j < 8; j++)
#pragma unroll
            for (int i = 0; i < 4; i++) sacc[j][i] = 0.f;

#pragma unroll
        for (int kk = 0; kk < 8; kk++) {
            uint4 af = *(const uint4*)&smu[AQ_OFF + ((wid * 8 + qg) * QSTR + kk * 4 + qt) * 4];
#pragma unroll
            for (int j = 0; j < 8; j++) {
                uint2 bf = *(const uint2*)&smu[AK_OFF + ((j * 8 + qg) * KSTR + kk * 4 + qt) * 2];
                mma_tf32(sacc[j], af.x, af.y, af.z, af.w, bf.x, bf.y);
            }
        }

        // ---- scale + biases + masks ----
#pragma unroll
        for (int j = 0; j < 8; j++) {
            const int c = j * 8 + 2 * qt;
            const int gc = s0 + c;
            float2 s1 = *(const float2*)(spA + gc);
            float2 s2 = *(const float2*)(spB + gc);
            float2 d1 = *(const float2*)(dbA + gc);
            float2 d2 = *(const float2*)(dbB + gc);
            float2 a1 = *(const float2*)(amA + gc);
            float2 a2 = *(const float2*)(amB + gc);
            const float mk0 = Ms[c], mk1 = Ms[c + 1];
            sacc[j][0] = sacc[j][0] * 0.125f + a1.x + s1.x + d1.x + mk0;
            sacc[j][1] = sacc[j][1] * 0.125f + a1.y + s1.y + d1.y + mk1;
            sacc[j][2] = sacc[j][2] * 0.125f + a2.x + s2.x + d2.x + mk0;
            sacc[j][3] = sacc[j][3] * 0.125f + a2.y + s2.y + d2.y + mk1;
        }

        // ---- online softmax ----
        float mx0 = mrow[0], mx1 = mrow[1];
#pragma unroll
        for (int j = 0; j < 8; j++) {
            mx0 = fmaxf(mx0, fmaxf(sacc[j][0], sacc[j][1]));
            mx1 = fmaxf(mx1, fmaxf(sacc[j][2], sacc[j][3]));
        }
        mx0 = fmaxf(mx0, __shfl_xor_sync(0xFFFFFFFFu, mx0, 1));
        mx0 = fmaxf(mx0, __shfl_xor_sync(0xFFFFFFFFu, mx0, 2));
        mx1 = fmaxf(mx1, __shfl_xor_sync(0xFFFFFFFFu, mx1, 1));
        mx1 = fmaxf(mx1, __shfl_xor_sync(0xFFFFFFFFu, mx1, 2));

        const float al0 = __expf(mrow[0] - mx0);
        const float al1 = __expf(mrow[1] - mx1);
        float ls0 = 0.f, ls1 = 0.f;
#pragma unroll
        for (int j = 0; j < 8; j++) {
            sacc[j][0] = __expf(sacc[j][0] - mx0);
            sacc[j][1] = __expf(sacc[j][1] - mx0);
            sacc[j][2] = __expf(sacc[j][2] - mx1);
            sacc[j][3] = __expf(sacc[j][3] - mx1);
            ls0 += sacc[j][0] + sacc[j][1];
            ls1 += sacc[j][2] + sacc[j][3];
        }
        ls0 += __shfl_xor_sync(0xFFFFFFFFu, ls0, 1);
        ls0 += __shfl_xor_sync(0xFFFFFFFFu, ls0, 2);
        ls1 += __shfl_xor_sync(0xFFFFFFFFu, ls1, 1);
        ls1 += __shfl_xor_sync(0xFFFFFFFFu, ls1, 2);
        mrow[0] = mx0; mrow[1] = mx1;
        lrow[0] = lrow[0] * al0 + ls0;
        lrow[1] = lrow[1] * al1 + ls1;
#pragma unroll
        for (int j = 0; j < 8; j++) {
            oacc[j][0] *= al0; oacc[j][1] *= al0;
            oacc[j][2] *= al1; oacc[j][3] *= al1;
        }

        // ---- P -> smem in A-fragment pair layout: Pp[c][qg] = (P[qg][c], P[qg+8][c]) ----
#pragma unroll
        for (int j = 0; j < 8; j++) {
            const int c = j * 8 + 2 * qt;
            uint2 p0 = {f2tf(sacc[j][0]), f2tf(sacc[j][2])};
            uint2 p1 = {f2tf(sacc[j][1]), f2tf(sacc[j][3])};
            *(uint2*)&smu[pwoff + (c * 8 + qg) * 2] = p0;
            *(uint2*)&smu[pwoff + ((c + 1) * 8 + qg) * 2] = p1;
        }
        __syncwarp();

        // ---- prefetch next K/V tile into registers (hidden under PV) ----
        if (s0 + 64 < S_) {
            const int sn = s0 + 64;
            const float* ks = kbase + (size_t)(sn + rK) * D_ + c0K;
#pragma unroll
            for (int i = 0; i < 4; i++) *(float4*)&kf[i * 4] = *(const float4*)(ks + i * 4);
            const float* v0 = vbase + (size_t)(sn + rV) * D_ + c0V;
            const float* v1 = vbase + (size_t)(sn + rV + 4) * D_ + c0V;
            *(float4*)&vf[0]  = *(const float4*)(v0);
            *(float4*)&vf[4]  = *(const float4*)(v0 + 4);
            *(float4*)&vf[8]  = *(const float4*)(v1);
            *(float4*)&vf[12] = *(const float4*)(v1 + 4);
        }

        // ---- PV: O += P[16 x 64] * V[64 x 64] ----
#pragma unroll
        for (int kk = 0; kk < 8; kk++) {
            const int ac = kk * 8 + qt;
            uint2 pa = *(const uint2*)&smu[pwoff + (ac * 8 + qg) * 2];
            uint2 pb = *(const uint2*)&smu[pwoff + ((ac + 4) * 8 + qg) * 2];
#pragma unroll
            for (int j = 0; j < 8; j++) {
                uint2 vv = *(const uint2*)&smu[AV_OFF + ((kk * 4 + qt) * VSTR + j * 8 + qg) * 2];
                mma_tf32(oacc[j], pa.x, pa.y, pb.x, pb.y, vv.x, vv.y);
            }
        }
    }

    // ---- epilogue ----
    const float inv0 = 1.f / lrow[0];
    const float inv1 = 1.f / lrow[1];
    float* oA = outp + (size_t)(b * T_ + ra) * E_ + h * D_;
    float* oB = outp + (size_t)(b * T_ + rb) * E_ + h * D_;
#pragma unroll
    for (int j = 0; j < 8; j++) {
        const int c = j * 8 + 2 * qt;
        float2 o0 = {oacc[j][0] * inv0, oacc[j][1] * inv0};
        float2 o1 = {oacc[j][2] * inv1, oacc[j][3] * inv1};
        *(float2*)(oA + c) = o0;
        *(float2*)(oB + c) = o1;
    }
}

// ---------------------------------------------------------------------------
extern "C" void kernel_launch(void* const* d_in, const int* in_sizes, int n_in,
                              void* d_out, int out_size)
{
    const float* query = (const float*)d_in[0];
    const float* key   = (const float*)d_in[1];
    const float* value = (const float*)d_in[2];
    const float* spatial = (const float*)d_in[3];
    const float* dirb    = (const float*)d_in[4];
    const unsigned char* pmask = (const unsigned char*)d_in[5];
    const float* amask = (const float*)d_in[6];
    const float* Wq = (const float*)d_in[7];
    const float* bq = (const float*)d_in[8];
    const float* Wk = (const float*)d_in[9];
    const float* bk = (const float*)d_in[10];
    const float* Wv = (const float*)d_in[11];
    const float* bv = (const float*)d_in[12];
    const float* Wo = (const float*)d_in[13];
    const float* bo = (const float*)d_in[14];
    float* out = (float*)d_out;

    float *qp, *kp, *vp, *ap;
    cudaGetSymbolAddress((void**)&qp, g_q);
    cudaGetSymbolAddress((void**)&kp, g_k);
    cudaGetSymbolAddress((void**)&vp, g_v);
    cudaGetSymbolAddress((void**)&ap, g_attn);

    cudaFuncSetAttribute(gemm_tc,
                         cudaFuncAttributeMaxDynamicSharedMemorySize,
                         GEMM_SMEM_BYTES);
    cudaFuncSetAttribute(attn_tc,
                         cudaFuncAttributeMaxDynamicSharedMemorySize,
                         ATTN_SMEM_BYTES);

    const dim3 gb(E_ / 64, M_ / 256);   // (16, 16)
    gemm_tc<<<gb, 256, GEMM_SMEM_BYTES>>>(query, Wq, bq, qp, 1);
    gemm_tc<<<gb, 256, GEMM_SMEM_BYTES>>>(key,   Wk, bk, kp, 1);
    gemm_tc<<<gb, 256, GEMM_SMEM_BYTES>>>(value, Wv, bv, vp, 1);

    attn_tc<<<dim3(T_ / 128, H_, B_), 256, ATTN_SMEM_BYTES>>>(
        spatial, dirb, amask, pmask, ap);

    gemm_tc<<<gb, 256, GEMM_SMEM_BYTES>>>(ap, Wo, bo, out, 0);
}

// round 6
// speedup vs baseline: 1.0475x; 1.0475x over previous
#include <cuda_runtime.h>
#include <cstdint>

#define B_ 2
#define T_ 2048
#define S_ 2048
#define E_ 1024
#define H_ 16
#define D_ 64
#define M_ (B_*T_)

// Scratch (device globals; no allocation allowed)
__device__ float g_q[B_*H_*T_*D_];     // holds tf32-bit floats, pre-scaled by 0.125
__device__ float g_k[B_*H_*S_*D_];     // holds tf32-bit floats
__device__ float g_v[B_*H_*S_*D_];     // holds tf32-bit floats
__device__ float g_attn[M_*E_];

// ---------------------------------------------------------------------------
// helpers
// ---------------------------------------------------------------------------
__device__ __forceinline__ uint32_t f2tf(float x) {
    uint32_t r;
    asm("cvt.rna.tf32.f32 %0, %1;" : "=r"(r) : "f"(x));
    return r;
}

__device__ __forceinline__ void mma_tf32(float c[4],
                                         uint32_t a0, uint32_t a1, uint32_t a2, uint32_t a3,
                                         uint32_t b0, uint32_t b1) {
    asm("mma.sync.aligned.m16n8k8.row.col.f32.tf32.tf32.f32 "
        "{%0,%1,%2,%3},{%4,%5,%6,%7},{%8,%9},{%0,%1,%2,%3};"
        : "+f"(c[0]), "+f"(c[1]), "+f"(c[2]), "+f"(c[3])
        : "r"(a0), "r"(a1), "r"(a2), "r"(a3), "r"(b0), "r"(b1));
}

__device__ __forceinline__ void cp16(void* smem_dst, const void* gmem_src) {
    uint32_t s = (uint32_t)__cvta_generic_to_shared(smem_dst);
    asm volatile("cp.async.cg.shared.global [%0], [%1], 16;" :: "r"(s), "l"(gmem_src));
}
__device__ __forceinline__ void cp_commit() {
    asm volatile("cp.async.commit_group;");
}
__device__ __forceinline__ void cp_wait0() {
    asm volatile("cp.async.wait_group 0;");
}
__device__ __forceinline__ void cp_wait1() {
    asm volatile("cp.async.wait_group 1;");
}

// ---------------------------------------------------------------------------
// GEMM (tf32 tensor, cp.async double-buffered):
// out[m][n] = (sum_k A[m][k]*W[n][k] + bias[n]) * scaleOut
// headMajor=1: head-major output, values stored as tf32-bit floats.
// ---------------------------------------------------------------------------
#define GEMM_SMEM_FLOATS (2*(256*36) + 2*(64*36))
#define GEMM_SMEM_BYTES  (GEMM_SMEM_FLOATS * 4)

__global__ void __launch_bounds__(256, 2) gemm_tc(
    const float* __restrict__ A, const float* __restrict__ W,
    const float* __restrict__ bias, float* __restrict__ out, int headMajor,
    float scaleOut)
{
    extern __shared__ float gsm[];
    float* As = gsm;                 // [2][256][36]
    float* Ws = gsm + 2 * 256 * 36;  // [2][64][36]

    const int tid  = threadIdx.x;
    const int lane = tid & 31;
    const int wid  = tid >> 5;
    const int m0   = blockIdx.y * 256;
    const int n0   = blockIdx.x * 64;
    const int qg   = lane >> 2;
    const int qt   = lane & 3;

    float acc[2][8][4];
#pragma unroll
    for (int mt = 0; mt < 2; mt++)
#pragma unroll
        for (int j = 0; j < 8; j++)
#pragma unroll
            for (int i = 0; i < 4; i++) acc[mt][j][i] = 0.f;

    const float* Arow = A + (size_t)(m0 + tid) * E_;
    const float* Wrow = W + (size_t)(n0 + (tid >> 2)) * E_ + (tid & 3) * 8;
    float* Asr = As + tid * 36;
    float* Wsr = Ws + (tid >> 2) * 36 + (tid & 3) * 8;

#pragma unroll
    for (int i = 0; i < 8; i++) cp16(Asr + i * 4, Arow + i * 4);
#pragma unroll
    for (int i = 0; i < 2; i++) cp16(Wsr + i * 4, Wrow + i * 4);
    cp_commit();

    const int NSTEP = E_ / 32;
    for (int s = 0; s < NSTEP; s++) {
        const int buf  = s & 1;
        const int nbuf = buf ^ 1;
        if (s + 1 < NSTEP) {
            const int kt = (s + 1) * 32;
#pragma unroll
            for (int i = 0; i < 8; i++)
                cp16(Asr + nbuf * 256 * 36 + i * 4, Arow + kt + i * 4);
#pragma unroll
            for (int i = 0; i < 2; i++)
                cp16(Wsr + nbuf * 64 * 36 + i * 4, Wrow + kt + i * 4);
            cp_commit();
            cp_wait1();
        } else {
            cp_wait0();
        }
        __syncthreads();

        const float* Ab = As + buf * 256 * 36;
        const float* Wb = Ws + buf * 64 * 36;
#pragma unroll
        for (int kk = 0; kk < 4; kk++) {
            uint32_t a[2][4];
#pragma unroll
            for (int mt = 0; mt < 2; mt++) {
                const int ar = wid * 32 + mt * 16 + qg;
                const int ac = kk * 8 + qt;
                a[mt][0] = f2tf(Ab[ar * 36 + ac]);
                a[mt][1] = f2tf(Ab[(ar + 8) * 36 + ac]);
                a[mt][2] = f2tf(Ab[ar * 36 + ac + 4]);
                a[mt][3] = f2tf(Ab[(ar + 8) * 36 + ac + 4]);
            }
#pragma unroll
            for (int j = 0; j < 8; j++) {
                const int br = j * 8 + qg;
                const int bc = kk * 8 + qt;
                uint32_t b0 = f2tf(Wb[br * 36 + bc]);
                uint32_t b1 = f2tf(Wb[br * 36 + bc + 4]);
                mma_tf32(acc[0][j], a[0][0], a[0][1], a[0][2], a[0][3], b0, b1);
                mma_tf32(acc[1][j], a[1][0], a[1][1], a[1][2], a[1][3], b0, b1);
            }
        }
        __syncthreads();
    }

#pragma unroll
    for (int mt = 0; mt < 2; mt++) {
        const int row0 = m0 + wid * 32 + mt * 16 + qg;
#pragma unroll
        for (int j = 0; j < 8; j++) {
            const int col = n0 + j * 8 + 2 * qt;
            const float bz0 = bias[col], bz1 = bias[col + 1];
            float v00 = (acc[mt][j][0] + bz0) * scaleOut;
            float v01 = (acc[mt][j][1] + bz1) * scaleOut;
            float v10 = (acc[mt][j][2] + bz0) * scaleOut;
            float v11 = (acc[mt][j][3] + bz1) * scaleOut;
            if (headMajor) {
                // store tf32-bit floats (pre-converted operands for attn)
                v00 = __uint_as_float(f2tf(v00));
                v01 = __uint_as_float(f2tf(v01));
                v10 = __uint_as_float(f2tf(v10));
                v11 = __uint_as_float(f2tf(v11));
                const int h = col >> 6, d = col & 63;
                {
                    const int b = row0 >> 11, t = row0 & 2047;
                    float2 o = {v00, v01};
                    *(float2*)&out[(size_t)((b * H_ + h) * T_ + t) * D_ + d] = o;
                }
                {
                    const int r1 = row0 + 8;
                    const int b = r1 >> 11, t = r1 & 2047;
                    float2 o = {v10, v11};
                    *(float2*)&out[(size_t)((b * H_ + h) * T_ + t) * D_ + d] = o;
                }
            } else {
                float2 o0 = {v00, v01};
                float2 o1 = {v10, v11};
                *(float2*)&out[(size_t)row0 * E_ + col] = o0;
                *(float2*)&out[(size_t)(row0 + 8) * E_ + col] = o1;
            }
        }
    }
}

// ---------------------------------------------------------------------------
// Flash attention, tf32 tensor cores.
// Grid (T/128, H, B), 256 threads = 8 warps; warp owns 16 full q-rows.
// Q/K/V already tf32 bits in gmem (Q pre-scaled by 1/8).
// K/V double-buffered via cp.async; bias LDGs hoisted above QK^T;
// P passes C-frag -> A-frag via quad shuffles (no smem round-trip).
// ---------------------------------------------------------------------------
#define AQ_OFF 0                         // Q  [128][68] u32
#define AK_OFF (128*68)                  // K  [2][64][68]
#define AV_OFF (AK_OFF + 2*64*68)        // V  [2][64][72]
#define AM_OFF (AV_OFF + 2*64*72)        // Ms [2][64] f32
#define ATTN_SMEM_U32 (AM_OFF + 128)
#define ATTN_SMEM_BYTES (ATTN_SMEM_U32 * 4)

__global__ void __launch_bounds__(256, 2) attn_tc(
    const float* __restrict__ spatial, const float* __restrict__ dirb,
    const float* __restrict__ amask, const unsigned char* __restrict__ pmask,
    float* __restrict__ outp)
{
    extern __shared__ uint32_t smu[];
    uint32_t* Qs = smu + AQ_OFF;
    uint32_t* Ks = smu + AK_OFF;
    uint32_t* Vs = smu + AV_OFF;
    float*    Ms = (float*)(smu + AM_OFF);

    const int tid  = threadIdx.x;
    const int lane = tid & 31;
    const int wid  = tid >> 5;
    const int qg   = lane >> 2;
    const int qt   = lane & 3;
    const int t0   = blockIdx.x * 128;
    const int h    = blockIdx.y;
    const int b    = blockIdx.z;
    const int r0   = wid * 16;

    const float* qbase = g_q + (size_t)((b * H_ + h) * T_ + t0) * D_;
    const float* kbase = g_k + (size_t)(b * H_ + h) * S_ * D_;
    const float* vbase = g_v + (size_t)(b * H_ + h) * S_ * D_;

    // staging roles
    const int rQ  = tid >> 1;          // Q row 0..127
    const int cQ  = (tid & 1) * 32;
    const int rK  = tid >> 2;          // K/V row 0..63
    const int cK  = (tid & 3) * 16;

    // ---- prologue: Q + K0/V0 + Ms0 ----
    {
        const float* src = qbase + rQ * D_ + cQ;
        uint32_t* dst = Qs + rQ * 68 + cQ;
#pragma unroll
        for (int i = 0; i < 8; i++) cp16(dst + i * 4, src + i * 4);
        const float* ks = kbase + (size_t)rK * D_ + cK;
        const float* vs = vbase + (size_t)rK * D_ + cK;
#pragma unroll
        for (int i = 0; i < 4; i++) cp16(Ks + rK * 68 + cK + i * 4, ks + i * 4);
#pragma unroll
        for (int i = 0; i < 4; i++) cp16(Vs + rK * 72 + cK + i * 4, vs + i * 4);
        cp_commit();
        if (tid < 64) Ms[tid] = pmask[b * S_ + tid] ? -1e30f : 0.f;
    }

    float mrow[2] = {-1e30f, -1e30f};
    float lrow[2] = {0.f, 0.f};
    float oacc[8][4];
#pragma unroll
    for (int j = 0; j < 8; j++)
#pragma unroll
        for (int i = 0; i < 4; i++) oacc[j][i] = 0.f;

    const int ra = t0 + r0 + qg;
    const int rb = ra + 8;
    const size_t bh = (size_t)(b * H_ + h) * T_;
    const float* spA = spatial + (bh + ra) * S_ + 2 * qt;
    const float* spB = spatial + (bh + rb) * S_ + 2 * qt;
    const float* dbA = dirb + (bh + ra) * S_ + 2 * qt;
    const float* dbB = dirb + (bh + rb) * S_ + 2 * qt;
    const float* amA = amask + (size_t)ra * S_ + 2 * qt;
    const float* amB = amask + (size_t)rb * S_ + 2 * qt;

    const int sl1 = qt >> 1;       // shuffle src within quad
    const int sl2 = sl1 + 2;
    const bool oddq = qt & 1;

    for (int it = 0; it < 32; it++) {
        const int s0  = it * 64;
        const int cur = it & 1;
        const int nxt = cur ^ 1;

        // issue next tile's K/V (buffer nxt was released by barrier #2 of it-1)
        if (it + 1 < 32) {
            const int sn = s0 + 64;
            const float* ks = kbase + (size_t)(sn + rK) * D_ + cK;
            const float* vs = vbase + (size_t)(sn + rK) * D_ + cK;
#pragma unroll
            for (int i = 0; i < 4; i++)
                cp16(Ks + nxt * 64 * 68 + rK * 68 + cK + i * 4, ks + i * 4);
#pragma unroll
            for (int i = 0; i < 4; i++)
                cp16(Vs + nxt * 64 * 72 + rK * 72 + cK + i * 4, vs + i * 4);
            cp_commit();
            if (tid < 64) Ms[nxt * 64 + tid] = pmask[b * S_ + sn + tid] ? -1e30f : 0.f;
            cp_wait1();
        } else {
            cp_wait0();
        }
        __syncthreads();   // barrier #1: tile it data visible everywhere

        // ---- hoisted bias loads (overlap with QK^T MMAs) ----
        float2 spa[8], spb[8], dba[8], dbb[8];
#pragma unroll
        for (int j = 0; j < 8; j++) {
            const int gc = s0 + j * 8;
            spa[j] = *(const float2*)(spA + gc);
            spb[j] = *(const float2*)(spB + gc);
            dba[j] = *(const float2*)(dbA + gc);
            dbb[j] = *(const float2*)(dbB + gc);
        }

        // ---- QK^T (Q pre-scaled by 1/8; operands already tf32 bits) ----
        const uint32_t* Kc = Ks + cur * 64 * 68;
        float sacc[8][4];
#pragma unroll
        for (int j = 0; j < 8; j++)
#pragma unroll
            for (int i = 0; i < 4; i++) sacc[j][i] = 0.f;

#pragma unroll
        for (int kk = 0; kk < 8; kk++) {
            const int ar = r0 + qg, ac = kk * 8 + qt;
            uint32_t a0 = Qs[ar * 68 + ac];
            uint32_t a1 = Qs[(ar + 8) * 68 + ac];
            uint32_t a2 = Qs[ar * 68 + ac + 4];
            uint32_t a3 = Qs[(ar + 8) * 68 + ac + 4];
#pragma unroll
            for (int j = 0; j < 8; j++) {
                const int br = j * 8 + qg;
                const int bc = kk * 8 + qt;
                uint32_t b0 = Kc[br * 68 + bc];
                uint32_t b1 = Kc[br * 68 + bc + 4];
                mma_tf32(sacc[j], a0, a1, a2, a3, b0, b1);
            }
        }

        // ---- biases + masks (amask is L2-resident; reused across 32 (b,h)) ----
#pragma unroll
        for (int j = 0; j < 8; j++) {
            const int c = j * 8 + 2 * qt;
            const int gc = s0 + j * 8;
            float2 a1v = *(const float2*)(amA + gc);
            float2 a2v = *(const float2*)(amB + gc);
            const float mk0 = Ms[cur * 64 + c], mk1 = Ms[cur * 64 + c + 1];
            sacc[j][0] = sacc[j][0] + a1v.x + spa[j].x + dba[j].x + mk0;
            sacc[j][1] = sacc[j][1] + a1v.y + spa[j].y + dba[j].y + mk1;
            sacc[j][2] = sacc[j][2] + a2v.x + spb[j].x + dbb[j].x + mk0;
            sacc[j][3] = sacc[j][3] + a2v.y + spb[j].y + dbb[j].y + mk1;
        }

        // ---- online softmax (row = 4 quad lanes) ----
        float mx0 = mrow[0], mx1 = mrow[1];
#pragma unroll
        for (int j = 0; j < 8; j++) {
            mx0 = fmaxf(mx0, fmaxf(sacc[j][0], sacc[j][1]));
            mx1 = fmaxf(mx1, fmaxf(sacc[j][2], sacc[j][3]));
        }
        mx0 = fmaxf(mx0, __shfl_xor_sync(0xFFFFFFFFu, mx0, 1));
        mx0 = fmaxf(mx0, __shfl_xor_sync(0xFFFFFFFFu, mx0, 2));
        mx1 = fmaxf(mx1, __shfl_xor_sync(0xFFFFFFFFu, mx1, 1));
        mx1 = fmaxf(mx1, __shfl_xor_sync(0xFFFFFFFFu, mx1, 2));

        const float al0 = __expf(mrow[0] - mx0);
        const float al1 = __expf(mrow[1] - mx1);
        float ls0 = 0.f, ls1 = 0.f;
#pragma unroll
        for (int j = 0; j < 8; j++) {
            sacc[j][0] = __expf(sacc[j][0] - mx0);
            sacc[j][1] = __expf(sacc[j][1] - mx0);
            sacc[j][2] = __expf(sacc[j][2] - mx1);
            sacc[j][3] = __expf(sacc[j][3] - mx1);
            ls0 += sacc[j][0] + sacc[j][1];
            ls1 += sacc[j][2] + sacc[j][3];
        }
        ls0 += __shfl_xor_sync(0xFFFFFFFFu, ls0, 1);
        ls0 += __shfl_xor_sync(0xFFFFFFFFu, ls0, 2);
        ls1 += __shfl_xor_sync(0xFFFFFFFFu, ls1, 1);
        ls1 += __shfl_xor_sync(0xFFFFFFFFu, ls1, 2);
        mrow[0] = mx0; mrow[1] = mx1;
        lrow[0] = lrow[0] * al0 + ls0;
        lrow[1] = lrow[1] * al1 + ls1;
#pragma unroll
        for (int j = 0; j < 8; j++) {
            oacc[j][0] *= al0; oacc[j][1] *= al0;
            oacc[j][2] *= al1; oacc[j][3] *= al1;
        }

        // ---- PV: A-frag via quad shuffles from C-frag sacc[kk] ----
        const uint32_t* Vc = Vs + cur * 64 * 72;
#pragma unroll
        for (int kk = 0; kk < 8; kk++) {
            uint32_t x0 = f2tf(sacc[kk][0]);
            uint32_t x1 = f2tf(sacc[kk][1]);
            uint32_t x2 = f2tf(sacc[kk][2]);
            uint32_t x3 = f2tf(sacc[kk][3]);
            uint32_t t00 = __shfl_sync(0xFFFFFFFFu, x0, sl1, 4);
            uint32_t t01 = __shfl_sync(0xFFFFFFFFu, x1, sl1, 4);
            uint32_t t02 = __shfl_sync(0xFFFFFFFFu, x2, sl1, 4);
            uint32_t t03 = __shfl_sync(0xFFFFFFFFu, x3, sl1, 4);
            uint32_t t10 = __shfl_sync(0xFFFFFFFFu, x0, sl2, 4);
            uint32_t t11 = __shfl_sync(0xFFFFFFFFu, x1, sl2, 4);
            uint32_t t12 = __shfl_sync(0xFFFFFFFFu, x2, sl2, 4);
            uint32_t t13 = __shfl_sync(0xFFFFFFFFu, x3, sl2, 4);
            uint32_t a0 = oddq ? t01 : t00;   // P[qg][8kk+qt]
            uint32_t a1 = oddq ? t03 : t02;   // P[qg+8][8kk+qt]
            uint32_t a2 = oddq ? t11 : t10;   // P[qg][8kk+qt+4]
            uint32_t a3 = oddq ? t13 : t12;   // P[qg+8][8kk+qt+4]
#pragma unroll
            for (int j = 0; j < 8; j++) {
                const int br = kk * 8 + qt;
                const int bc = j * 8 + qg;
                uint32_t b0 = Vc[br * 72 + bc];
                uint32_t b1 = Vc[(br + 4) * 72 + bc];
                mma_tf32(oacc[j], a0, a1, a2, a3, b0, b1);
            }
        }
        __syncthreads();   // barrier #2: release buffer cur for iteration it+1
    }

    // ---- epilogue ----
    const float inv0 = 1.f / lrow[0];
    const float inv1 = 1.f / lrow[1];
    float* oA = outp + (size_t)(b * T_ + ra) * E_ + h * D_;
    float* oB = outp + (size_t)(b * T_ + rb) * E_ + h * D_;
#pragma unroll
    for (int j = 0; j < 8; j++) {
        const int c = j * 8 + 2 * qt;
        float2 o0 = {oacc[j][0] * inv0, oacc[j][1] * inv0};
        float2 o1 = {oacc[j][2] * inv1, oacc[j][3] * inv1};
        *(float2*)(oA + c) = o0;
        *(float2*)(oB + c) = o1;
    }
}

// ---------------------------------------------------------------------------
extern "C" void kernel_launch(void* const* d_in, const int* in_sizes, int n_in,
                              void* d_out, int out_size)
{
    const float* query = (const float*)d_in[0];
    const float* key   = (const float*)d_in[1];
    const float* value = (const float*)d_in[2];
    const float* spatial = (const float*)d_in[3];
    const float* dirb    = (const float*)d_in[4];
    const unsigned char* pmask = (const unsigned char*)d_in[5];
    const float* amask = (const float*)d_in[6];
    const float* Wq = (const float*)d_in[7];
    const float* bq = (const float*)d_in[8];
    const float* Wk = (const float*)d_in[9];
    const float* bk = (const float*)d_in[10];
    const float* Wv = (const float*)d_in[11];
    const float* bv = (const float*)d_in[12];
    const float* Wo = (const float*)d_in[13];
    const float* bo = (const float*)d_in[14];
    float* out = (float*)d_out;

    float *qp, *kp, *vp, *ap;
    cudaGetSymbolAddress((void**)&qp, g_q);
    cudaGetSymbolAddress((void**)&kp, g_k);
    cudaGetSymbolAddress((void**)&vp, g_v);
    cudaGetSymbolAddress((void**)&ap, g_attn);

    cudaFuncSetAttribute(gemm_tc,
                         cudaFuncAttributeMaxDynamicSharedMemorySize,
                         GEMM_SMEM_BYTES);
    cudaFuncSetAttribute(attn_tc,
                         cudaFuncAttributeMaxDynamicSharedMemorySize,
                         ATTN_SMEM_BYTES);

    const dim3 gb(E_ / 64, M_ / 256);   // (16, 16)
    // Q projection pre-scaled by 1/sqrt(D)=0.125 (exact power of 2, folded)
    gemm_tc<<<gb, 256, GEMM_SMEM_BYTES>>>(query, Wq, bq, qp, 1, 0.125f);
    gemm_tc<<<gb, 256, GEMM_SMEM_BYTES>>>(key,   Wk, bk, kp, 1, 1.0f);
    gemm_tc<<<gb, 256, GEMM_SMEM_BYTES>>>(value, Wv, bv, vp, 1, 1.0f);

    attn_tc<<<dim3(T_ / 128, H_, B_), 256, ATTN_SMEM_BYTES>>>(
        spatial, dirb, amask, pmask, ap);

    gemm_tc<<<gb, 256, GEMM_SMEM_BYTES>>>(ap, Wo, bo, out, 0, 1.0f);
}

// round 7
// speedup vs baseline: 1.0892x; 1.0398x over previous
#include <cuda_runtime.h>
#include <cstdint>

#define B_ 2
#define T_ 2048
#define S_ 2048
#define E_ 1024
#define H_ 16
#define D_ 64
#define M_ (B_*T_)

// Scratch (device globals; no allocation allowed)
__device__ float g_q[B_*H_*T_*D_];     // tf32-bit floats, pre-scaled by 0.125
__device__ float g_k[B_*H_*S_*D_];     // tf32-bit floats
__device__ float g_v[B_*H_*S_*D_];     // tf32-bit floats
__device__ float g_attn[M_*E_];

// ---------------------------------------------------------------------------
// helpers
// ---------------------------------------------------------------------------
__device__ __forceinline__ uint32_t f2tf(float x) {
    uint32_t r;
    asm("cvt.rna.tf32.f32 %0, %1;" : "=r"(r) : "f"(x));
    return r;
}

__device__ __forceinline__ void mma_tf32(float c[4],
                                         uint32_t a0, uint32_t a1, uint32_t a2, uint32_t a3,
                                         uint32_t b0, uint32_t b1) {
    asm("mma.sync.aligned.m16n8k8.row.col.f32.tf32.tf32.f32 "
        "{%0,%1,%2,%3},{%4,%5,%6,%7},{%8,%9},{%0,%1,%2,%3};"
        : "+f"(c[0]), "+f"(c[1]), "+f"(c[2]), "+f"(c[3])
        : "r"(a0), "r"(a1), "r"(a2), "r"(a3), "r"(b0), "r"(b1));
}

__device__ __forceinline__ void cp16(void* smem_dst, const void* gmem_src) {
    uint32_t s = (uint32_t)__cvta_generic_to_shared(smem_dst);
    asm volatile("cp.async.cg.shared.global [%0], [%1], 16;" :: "r"(s), "l"(gmem_src));
}
__device__ __forceinline__ void cp_commit() {
    asm volatile("cp.async.commit_group;");
}
__device__ __forceinline__ void cp_wait0() {
    asm volatile("cp.async.wait_group 0;");
}
__device__ __forceinline__ void cp_wait1() {
    asm volatile("cp.async.wait_group 1;");
}

// ---------------------------------------------------------------------------
// GEMM (tf32 tensor, cp.async double-buffered) — unchanged from R6
// ---------------------------------------------------------------------------
#define GEMM_SMEM_FLOATS (2*(256*36) + 2*(64*36))
#define GEMM_SMEM_BYTES  (GEMM_SMEM_FLOATS * 4)

__global__ void __launch_bounds__(256, 2) gemm_tc(
    const float* __restrict__ A, const float* __restrict__ W,
    const float* __restrict__ bias, float* __restrict__ out, int headMajor,
    float scaleOut)
{
    extern __shared__ float gsm[];
    float* As = gsm;                 // [2][256][36]
    float* Ws = gsm + 2 * 256 * 36;  // [2][64][36]

    const int tid  = threadIdx.x;
    const int lane = tid & 31;
    const int wid  = tid >> 5;
    const int m0   = blockIdx.y * 256;
    const int n0   = blockIdx.x * 64;
    const int qg   = lane >> 2;
    const int qt   = lane & 3;

    float acc[2][8][4];
#pragma unroll
    for (int mt = 0; mt < 2; mt++)
#pragma unroll
        for (int j = 0; j < 8; j++)
#pragma unroll
            for (int i = 0; i < 4; i++) acc[mt][j][i] = 0.f;

    const float* Arow = A + (size_t)(m0 + tid) * E_;
    const float* Wrow = W + (size_t)(n0 + (tid >> 2)) * E_ + (tid & 3) * 8;
    float* Asr = As + tid * 36;
    float* Wsr = Ws + (tid >> 2) * 36 + (tid & 3) * 8;

#pragma unroll
    for (int i = 0; i < 8; i++) cp16(Asr + i * 4, Arow + i * 4);
#pragma unroll
    for (int i = 0; i < 2; i++) cp16(Wsr + i * 4, Wrow + i * 4);
    cp_commit();

    const int NSTEP = E_ / 32;
    for (int s = 0; s < NSTEP; s++) {
        const int buf  = s & 1;
        const int nbuf = buf ^ 1;
        if (s + 1 < NSTEP) {
            const int kt = (s + 1) * 32;
#pragma unroll
            for (int i = 0; i < 8; i++)
                cp16(Asr + nbuf * 256 * 36 + i * 4, Arow + kt + i * 4);
#pragma unroll
            for (int i = 0; i < 2; i++)
                cp16(Wsr + nbuf * 64 * 36 + i * 4, Wrow + kt + i * 4);
            cp_commit();
            cp_wait1();
        } else {
            cp_wait0();
        }
        __syncthreads();

        const float* Ab = As + buf * 256 * 36;
        const float* Wb = Ws + buf * 64 * 36;
#pragma unroll
        for (int kk = 0; kk < 4; kk++) {
            uint32_t a[2][4];
#pragma unroll
            for (int mt = 0; mt < 2; mt++) {
                const int ar = wid * 32 + mt * 16 + qg;
                const int ac = kk * 8 + qt;
                a[mt][0] = f2tf(Ab[ar * 36 + ac]);
                a[mt][1] = f2tf(Ab[(ar + 8) * 36 + ac]);
                a[mt][2] = f2tf(Ab[ar * 36 + ac + 4]);
                a[mt][3] = f2tf(Ab[(ar + 8) * 36 + ac + 4]);
            }
#pragma unroll
            for (int j = 0; j < 8; j++) {
                const int br = j * 8 + qg;
                const int bc = kk * 8 + qt;
                uint32_t b0 = f2tf(Wb[br * 36 + bc]);
                uint32_t b1 = f2tf(Wb[br * 36 + bc + 4]);
                mma_tf32(acc[0][j], a[0][0], a[0][1], a[0][2], a[0][3], b0, b1);
                mma_tf32(acc[1][j], a[1][0], a[1][1], a[1][2], a[1][3], b0, b1);
            }
        }
        __syncthreads();
    }

#pragma unroll
    for (int mt = 0; mt < 2; mt++) {
        const int row0 = m0 + wid * 32 + mt * 16 + qg;
#pragma unroll
        for (int j = 0; j < 8; j++) {
            const int col = n0 + j * 8 + 2 * qt;
            const float bz0 = bias[col], bz1 = bias[col + 1];
            float v00 = (acc[mt][j][0] + bz0) * scaleOut;
            float v01 = (acc[mt][j][1] + bz1) * scaleOut;
            float v10 = (acc[mt][j][2] + bz0) * scaleOut;
            float v11 = (acc[mt][j][3] + bz1) * scaleOut;
            if (headMajor) {
                v00 = __uint_as_float(f2tf(v00));
                v01 = __uint_as_float(f2tf(v01));
                v10 = __uint_as_float(f2tf(v10));
                v11 = __uint_as_float(f2tf(v11));
                const int h = col >> 6, d = col & 63;
                {
                    const int b = row0 >> 11, t = row0 & 2047;
                    float2 o = {v00, v01};
                    *(float2*)&out[(size_t)((b * H_ + h) * T_ + t) * D_ + d] = o;
                }
                {
                    const int r1 = row0 + 8;
                    const int b = r1 >> 11, t = r1 & 2047;
                    float2 o = {v10, v11};
                    *(float2*)&out[(size_t)((b * H_ + h) * T_ + t) * D_ + d] = o;
                }
            } else {
                float2 o0 = {v00, v01};
                float2 o1 = {v10, v11};
                *(float2*)&out[(size_t)row0 * E_ + col] = o0;
                *(float2*)&out[(size_t)(row0 + 8) * E_ + col] = o1;
            }
        }
    }
}

// ---------------------------------------------------------------------------
// Flash attention, tf32 tensor cores, S-tile = 32.
// Grid (T/128, H, B), 256 threads = 8 warps; warp owns 16 full q-rows.
// Biases (spatial+directional) stream via cp.async into a warp-private smem
// slot one tile ahead (deep MLP, no register cost). K/V double-buffered.
// ---------------------------------------------------------------------------
#define ST_ 32                            // s-tile
#define NT_ (S_/ST_)                      // 64 tiles
#define AQ_OFF  0                         // Q  [128][68]
#define AK_OFF  (128*68)                  // K  [2][32][68]
#define AKBUF   (32*68)
#define AV_OFF  (AK_OFF + 2*AKBUF)        // V  [2][32][72]
#define AVBUF   (32*72)
#define ASP_OFF (AV_OFF + 2*AVBUF)        // SP [128][36]
#define ADB_OFF (ASP_OFF + 128*36)        // DB [128][36]
#define AM_OFF  (ADB_OFF + 128*36)        // Ms [2][32]
#define ATTN_SMEM_U32 (AM_OFF + 64)
#define ATTN_SMEM_BYTES (ATTN_SMEM_U32 * 4)   // 107,776 B -> 2 CTAs/SM

__global__ void __launch_bounds__(256, 2) attn_tc(
    const float* __restrict__ spatial, const float* __restrict__ dirb,
    const float* __restrict__ amask, const unsigned char* __restrict__ pmask,
    float* __restrict__ outp)
{
    extern __shared__ uint32_t smu[];
    uint32_t* Qs  = smu + AQ_OFF;
    uint32_t* Ks  = smu + AK_OFF;
    uint32_t* Vs  = smu + AV_OFF;
    float*    SPs = (float*)(smu + ASP_OFF);
    float*    DBs = (float*)(smu + ADB_OFF);
    float*    Ms  = (float*)(smu + AM_OFF);

    const int tid  = threadIdx.x;
    const int lane = tid & 31;
    const int wid  = tid >> 5;
    const int qg   = lane >> 2;
    const int qt   = lane & 3;
    const int t0   = blockIdx.x * 128;
    const int h    = blockIdx.y;
    const int b    = blockIdx.z;
    const int r0   = wid * 16;

    const float* qbase = g_q + (size_t)((b * H_ + h) * T_ + t0) * D_;
    const float* kbase = g_k + (size_t)(b * H_ + h) * S_ * D_;
    const float* vbase = g_v + (size_t)(b * H_ + h) * S_ * D_;

    // staging roles
    const int rQ  = tid >> 1, cQ = (tid & 1) * 32;     // Q rows
    const int rKV = tid >> 3, cKV = (tid & 7) * 8;     // K/V rows (0..31)
    const int biasRow = r0 + (lane >> 1);              // warp-private bias row
    const int biasC4  = (lane & 1) * 4;                // chunk group (of 8 chunks)
    const size_t bh = (size_t)(b * H_ + h) * T_;
    const float* spRow = spatial + (bh + t0 + biasRow) * S_;
    const float* dbRow = dirb    + (bh + t0 + biasRow) * S_;
    float* spDst = SPs + biasRow * 36;
    float* dbDst = DBs + biasRow * 36;

    // ---- prologue: Q + K0/V0 + bias0 + Ms0 ----
    {
        const float* src = qbase + rQ * D_ + cQ;
        uint32_t* dst = Qs + rQ * 68 + cQ;
#pragma unroll
        for (int i = 0; i < 8; i++) cp16(dst + i * 4, src + i * 4);
        const float* ks = kbase + (size_t)rKV * D_ + cKV;
        const float* vs = vbase + (size_t)rKV * D_ + cKV;
        cp16(Ks + rKV * 68 + cKV,     ks);
        cp16(Ks + rKV * 68 + cKV + 4, ks + 4);
        cp16(Vs + rKV * 72 + cKV,     vs);
        cp16(Vs + rKV * 72 + cKV + 4, vs + 4);
#pragma unroll
        for (int t = 0; t < 4; t++) {
            const int c4 = (biasC4 + t) * 4;
            cp16(spDst + c4, spRow + c4);
            cp16(dbDst + c4, dbRow + c4);
        }
        cp_commit();
        if (tid < 32) Ms[tid] = pmask[b * S_ + tid] ? -1e30f : 0.f;
    }

    float mrow[2] = {-1e30f, -1e30f};
    float lrow[2] = {0.f, 0.f};
    float oacc[8][4];
#pragma unroll
    for (int j = 0; j < 8; j++)
#pragma unroll
        for (int i = 0; i < 4; i++) oacc[j][i] = 0.f;

    const int ra = t0 + r0 + qg;
    const int rb = ra + 8;
    const float* amA = amask + (size_t)ra * S_ + 2 * qt;
    const float* amB = amask + (size_t)rb * S_ + 2 * qt;

    const int sl1 = qt >> 1;
    const int sl2 = sl1 + 2;
    const bool oddq = qt & 1;

    for (int it = 0; it < NT_; it++) {
        const int s0  = it * ST_;
        const int cur = it & 1;
        const int nxt = cur ^ 1;

        cp_wait0();            // K/V(it) + bias(it) ready
        __syncthreads();       // single barrier per tile

        // ---- issue K/V(it+1); prefetch pmask(it+1) ----
        unsigned char pm = 0;
        if (it + 1 < NT_) {
            const int sn = s0 + ST_;
            const float* ks = kbase + (size_t)(sn + rKV) * D_ + cKV;
            const float* vs = vbase + (size_t)(sn + rKV) * D_ + cKV;
            cp16(Ks + nxt * AKBUF + rKV * 68 + cKV,     ks);
            cp16(Ks + nxt * AKBUF + rKV * 68 + cKV + 4, ks + 4);
            cp16(Vs + nxt * AVBUF + rKV * 72 + cKV,     vs);
            cp16(Vs + nxt * AVBUF + rKV * 72 + cKV + 4, vs + 4);
            cp_commit();
            if (tid < 32) pm = pmask[b * S_ + sn + tid];
        }

        // ---- hoisted amask loads (L2-resident) ----
        float2 am1[4], am2[4];
#pragma unroll
        for (int j = 0; j < 4; j++) {
            am1[j] = *(const float2*)(amA + s0 + j * 8);
            am2[j] = *(const float2*)(amB + s0 + j * 8);
        }

        // ---- QK^T: S[16 x 32] per warp ----
        const uint32_t* Kc = Ks + cur * AKBUF;
        float sacc[4][4];
#pragma unroll
        for (int j = 0; j < 4; j++)
#pragma unroll
            for (int i = 0; i < 4; i++) sacc[j][i] = 0.f;

#pragma unroll
        for (int kk = 0; kk < 8; kk++) {
            const int ar = r0 + qg, ac = kk * 8 + qt;
            uint32_t a0 = Qs[ar * 68 + ac];
            uint32_t a1 = Qs[(ar + 8) * 68 + ac];
            uint32_t a2 = Qs[ar * 68 + ac + 4];
            uint32_t a3 = Qs[(ar + 8) * 68 + ac + 4];
#pragma unroll
            for (int j = 0; j < 4; j++) {
                const int br = j * 8 + qg;
                uint32_t b0 = Kc[br * 68 + ac];
                uint32_t b1 = Kc[br * 68 + ac + 4];
                mma_tf32(sacc[j], a0, a1, a2, a3, b0, b1);
            }
        }

        // ---- add biases (from smem) + amask + pad mask ----
        const float* SPr0 = SPs + (r0 + qg) * 36;
        const float* SPr8 = SPs + (r0 + qg + 8) * 36;
        const float* DBr0 = DBs + (r0 + qg) * 36;
        const float* DBr8 = DBs + (r0 + qg + 8) * 36;
#pragma unroll
        for (int j = 0; j < 4; j++) {
            const int c = j * 8 + 2 * qt;
            float2 sp1 = *(const float2*)(SPr0 + c);
            float2 sp2 = *(const float2*)(SPr8 + c);
            float2 db1 = *(const float2*)(DBr0 + c);
            float2 db2 = *(const float2*)(DBr8 + c);
            const float mk0 = Ms[cur * 32 + c], mk1 = Ms[cur * 32 + c + 1];
            sacc[j][0] = sacc[j][0] + am1[j].x + sp1.x + db1.x + mk0;
            sacc[j][1] = sacc[j][1] + am1[j].y + sp1.y + db1.y + mk1;
            sacc[j][2] = sacc[j][2] + am2[j].x + sp2.x + db2.x + mk0;
            sacc[j][3] = sacc[j][3] + am2[j].y + sp2.y + db2.y + mk1;
        }

        // ---- issue bias(it+1) into the (now consumed, warp-private) slot ----
        if (it + 1 < NT_) {
            const int sn = s0 + ST_;
#pragma unroll
            for (int t = 0; t < 4; t++) {
                const int c4 = (biasC4 + t) * 4;
                cp16(spDst + c4, spRow + sn + c4);
                cp16(dbDst + c4, dbRow + sn + c4);
            }
            cp_commit();
        }

        // ---- online softmax ----
        float mx0 = mrow[0], mx1 = mrow[1];
#pragma unroll
        for (int j = 0; j < 4; j++) {
            mx0 = fmaxf(mx0, fmaxf(sacc[j][0], sacc[j][1]));
            mx1 = fmaxf(mx1, fmaxf(sacc[j][2], sacc[j][3]));
        }
        mx0 = fmaxf(mx0, __shfl_xor_sync(0xFFFFFFFFu, mx0, 1));
        mx0 = fmaxf(mx0, __shfl_xor_sync(0xFFFFFFFFu, mx0, 2));
        mx1 = fmaxf(mx1, __shfl_xor_sync(0xFFFFFFFFu, mx1, 1));
        mx1 = fmaxf(mx1, __shfl_xor_sync(0xFFFFFFFFu, mx1, 2));

        const float al0 = __expf(mrow[0] - mx0);
        const float al1 = __expf(mrow[1] - mx1);
        float ls0 = 0.f, ls1 = 0.f;
#pragma unroll
        for (int j = 0; j < 4; j++) {
            sacc[j][0] = __expf(sacc[j][0] - mx0);
            sacc[j][1] = __expf(sacc[j][1] - mx0);
            sacc[j][2] = __expf(sacc[j][2] - mx1);
            sacc[j][3] = __expf(sacc[j][3] - mx1);
            ls0 += sacc[j][0] + sacc[j][1];
            ls1 += sacc[j][2] + sacc[j][3];
        }
        ls0 += __shfl_xor_sync(0xFFFFFFFFu, ls0, 1);
        ls0 += __shfl_xor_sync(0xFFFFFFFFu, ls0, 2);
        ls1 += __shfl_xor_sync(0xFFFFFFFFu, ls1, 1);
        ls1 += __shfl_xor_sync(0xFFFFFFFFu, ls1, 2);
        mrow[0] = mx0; mrow[1] = mx1;
        lrow[0] = lrow[0] * al0 + ls0;
        lrow[1] = lrow[1] * al1 + ls1;
#pragma unroll
        for (int j = 0; j < 8; j++) {
            oacc[j][0] *= al0; oacc[j][1] *= al0;
            oacc[j][2] *= al1; oacc[j][3] *= al1;
        }

        // ---- PV: quad-shuffle transpose of P fragments, then MMA ----
        const uint32_t* Vc = Vs + cur * AVBUF;
#pragma unroll
        for (int kk = 0; kk < 4; kk++) {
            uint32_t x0 = f2tf(sacc[kk][0]);
            uint32_t x1 = f2tf(sacc[kk][1]);
            uint32_t x2 = f2tf(sacc[kk][2]);
            uint32_t x3 = f2tf(sacc[kk][3]);
            uint32_t t00 = __shfl_sync(0xFFFFFFFFu, x0, sl1, 4);
            uint32_t t01 = __shfl_sync(0xFFFFFFFFu, x1, sl1, 4);
            uint32_t t02 = __shfl_sync(0xFFFFFFFFu, x2, sl1, 4);
            uint32_t t03 = __shfl_sync(0xFFFFFFFFu, x3, sl1, 4);
            uint32_t t10 = __shfl_sync(0xFFFFFFFFu, x0, sl2, 4);
            uint32_t t11 = __shfl_sync(0xFFFFFFFFu, x1, sl2, 4);
            uint32_t t12 = __shfl_sync(0xFFFFFFFFu, x2, sl2, 4);
            uint32_t t13 = __shfl_sync(0xFFFFFFFFu, x3, sl2, 4);
            uint32_t a0 = oddq ? t01 : t00;
            uint32_t a1 = oddq ? t03 : t02;
            uint32_t a2 = oddq ? t11 : t10;
            uint32_t a3 = oddq ? t13 : t12;
            const int br = kk * 8 + qt;
#pragma unroll
            for (int j = 0; j < 8; j++) {
                const int bc = j * 8 + qg;
                uint32_t b0 = Vc[br * 72 + bc];
                uint32_t b1 = Vc[(br + 4) * 72 + bc];
                mma_tf32(oacc[j], a0, a1, a2, a3, b0, b1);
            }
        }

        // ---- store pad mask for next tile ----
        if (it + 1 < NT_ && tid < 32)
            Ms[nxt * 32 + tid] = pm ? -1e30f : 0.f;
    }

    // ---- epilogue ----
    const float inv0 = 1.f / lrow[0];
    const float inv1 = 1.f / lrow[1];
    float* oA = outp + (size_t)(b * T_ + ra) * E_ + h * D_;
    float* oB = outp + (size_t)(b * T_ + rb) * E_ + h * D_;
#pragma unroll
    for (int j = 0; j < 8; j++) {
        const int c = j * 8 + 2 * qt;
        float2 o0 = {oacc[j][0] * inv0, oacc[j][1] * inv0};
        float2 o1 = {oacc[j][2] * inv1, oacc[j][3] * inv1};
        *(float2*)(oA + c) = o0;
        *(float2*)(oB + c) = o1;
    }
}

// ---------------------------------------------------------------------------
extern "C" void kernel_launch(void* const* d_in, const int* in_sizes, int n_in,
                              void* d_out, int out_size)
{
    const float* query = (const float*)d_in[0];
    const float* key   = (const float*)d_in[1];
    const float* value = (const float*)d_in[2];
    const float* spatial = (const float*)d_in[3];
    const float* dirb    = (const float*)d_in[4];
    const unsigned char* pmask = (const unsigned char*)d_in[5];
    const float* amask = (const float*)d_in[6];
    const float* Wq = (const float*)d_in[7];
    const float* bq = (const float*)d_in[8];
    const float* Wk = (const float*)d_in[9];
    const float* bk = (const float*)d_in[10];
    const float* Wv = (const float*)d_in[11];
    const float* bv = (const float*)d_in[12];
    const float* Wo = (const float*)d_in[13];
    const float* bo = (const float*)d_in[14];
    float* out = (float*)d_out;

    float *qp, *kp, *vp, *ap;
    cudaGetSymbolAddress((void**)&qp, g_q);
    cudaGetSymbolAddress((void**)&kp, g_k);
    cudaGetSymbolAddress((void**)&vp, g_v);
    cudaGetSymbolAddress((void**)&ap, g_attn);

    cudaFuncSetAttribute(gemm_tc,
                         cudaFuncAttributeMaxDynamicSharedMemorySize,
                         GEMM_SMEM_BYTES);
    cudaFuncSetAttribute(attn_tc,
                         cudaFuncAttributeMaxDynamicSharedMemorySize,
                         ATTN_SMEM_BYTES);

    const dim3 gb(E_ / 64, M_ / 256);   // (16, 16)
    gemm_tc<<<gb, 256, GEMM_SMEM_BYTES>>>(query, Wq, bq, qp, 1, 0.125f);
    gemm_tc<<<gb, 256, GEMM_SMEM_BYTES>>>(key,   Wk, bk, kp, 1, 1.0f);
    gemm_tc<<<gb, 256, GEMM_SMEM_BYTES>>>(value, Wv, bv, vp, 1, 1.0f);

    attn_tc<<<dim3(T_ / 128, H_, B_), 256, ATTN_SMEM_BYTES>>>(
        spatial, dirb, amask, pmask, ap);

    gemm_tc<<<gb, 256, GEMM_SMEM_BYTES>>>(ap, Wo, bo, out, 0, 1.0f);
}

// round 8
// speedup vs baseline: 1.0901x; 1.0008x over previous
#include <cuda_runtime.h>
#include <cstdint>

#define B_ 2
#define T_ 2048
#define S_ 2048
#define E_ 1024
#define H_ 16
#define D_ 64
#define M_ (B_*T_)

// Scratch (device globals; no allocation allowed)
__device__ float g_q[B_*H_*T_*D_];     // tf32-bit floats, pre-scaled by 0.125
__device__ float g_k[B_*H_*S_*D_];     // tf32-bit floats
__device__ float g_v[B_*H_*S_*D_];     // tf32-bit floats
__device__ float g_attn[M_*E_];

// ---------------------------------------------------------------------------
// helpers
// ---------------------------------------------------------------------------
__device__ __forceinline__ uint32_t f2tf(float x) {
    uint32_t r;
    asm("cvt.rna.tf32.f32 %0, %1;" : "=r"(r) : "f"(x));
    return r;
}

__device__ __forceinline__ void mma_tf32(float c[4],
                                         uint32_t a0, uint32_t a1, uint32_t a2, uint32_t a3,
                                         uint32_t b0, uint32_t b1) {
    asm("mma.sync.aligned.m16n8k8.row.col.f32.tf32.tf32.f32 "
        "{%0,%1,%2,%3},{%4,%5,%6,%7},{%8,%9},{%0,%1,%2,%3};"
        : "+f"(c[0]), "+f"(c[1]), "+f"(c[2]), "+f"(c[3])
        : "r"(a0), "r"(a1), "r"(a2), "r"(a3), "r"(b0), "r"(b1));
}

__device__ __forceinline__ void cp16(void* smem_dst, const void* gmem_src) {
    uint32_t s = (uint32_t)__cvta_generic_to_shared(smem_dst);
    asm volatile("cp.async.cg.shared.global [%0], [%1], 16;" :: "r"(s), "l"(gmem_src));
}
__device__ __forceinline__ void cp_commit() {
    asm volatile("cp.async.commit_group;");
}
__device__ __forceinline__ void cp_wait0() {
    asm volatile("cp.async.wait_group 0;");
}
__device__ __forceinline__ void cp_wait1() {
    asm volatile("cp.async.wait_group 1;");
}

// ---------------------------------------------------------------------------
// GEMM (tf32 tensor, cp.async double-buffered) — unchanged from R6
// ---------------------------------------------------------------------------
#define GEMM_SMEM_FLOATS (2*(256*36) + 2*(64*36))
#define GEMM_SMEM_BYTES  (GEMM_SMEM_FLOATS * 4)

__global__ void __launch_bounds__(256, 2) gemm_tc(
    const float* __restrict__ A, const float* __restrict__ W,
    const float* __restrict__ bias, float* __restrict__ out, int headMajor,
    float scaleOut)
{
    extern __shared__ float gsm[];
    float* As = gsm;                 // [2][256][36]
    float* Ws = gsm + 2 * 256 * 36;  // [2][64][36]

    const int tid  = threadIdx.x;
    const int lane = tid & 31;
    const int wid  = tid >> 5;
    const int m0   = blockIdx.y * 256;
    const int n0   = blockIdx.x * 64;
    const int qg   = lane >> 2;
    const int qt   = lane & 3;

    float acc[2][8][4];
#pragma unroll
    for (int mt = 0; mt < 2; mt++)
#pragma unroll
        for (int j = 0; j < 8; j++)
#pragma unroll
            for (int i = 0; i < 4; i++) acc[mt][j][i] = 0.f;

    const float* Arow = A + (size_t)(m0 + tid) * E_;
    const float* Wrow = W + (size_t)(n0 + (tid >> 2)) * E_ + (tid & 3) * 8;
    float* Asr = As + tid * 36;
    float* Wsr = Ws + (tid >> 2) * 36 + (tid & 3) * 8;

#pragma unroll
    for (int i = 0; i < 8; i++) cp16(Asr + i * 4, Arow + i * 4);
#pragma unroll
    for (int i = 0; i < 2; i++) cp16(Wsr + i * 4, Wrow + i * 4);
    cp_commit();

    const int NSTEP = E_ / 32;
    for (int s = 0; s < NSTEP; s++) {
        const int buf  = s & 1;
        const int nbuf = buf ^ 1;
        if (s + 1 < NSTEP) {
            const int kt = (s + 1) * 32;
#pragma unroll
            for (int i = 0; i < 8; i++)
                cp16(Asr + nbuf * 256 * 36 + i * 4, Arow + kt + i * 4);
#pragma unroll
            for (int i = 0; i < 2; i++)
                cp16(Wsr + nbuf * 64 * 36 + i * 4, Wrow + kt + i * 4);
            cp_commit();
            cp_wait1();
        } else {
            cp_wait0();
        }
        __syncthreads();

        const float* Ab = As + buf * 256 * 36;
        const float* Wb = Ws + buf * 64 * 36;
#pragma unroll
        for (int kk = 0; kk < 4; kk++) {
            uint32_t a[2][4];
#pragma unroll
            for (int mt = 0; mt < 2; mt++) {
                const int ar = wid * 32 + mt * 16 + qg;
                const int ac = kk * 8 + qt;
                a[mt][0] = f2tf(Ab[ar * 36 + ac]);
                a[mt][1] = f2tf(Ab[(ar + 8) * 36 + ac]);
                a[mt][2] = f2tf(Ab[ar * 36 + ac + 4]);
                a[mt][3] = f2tf(Ab[(ar + 8) * 36 + ac + 4]);
            }
#pragma unroll
            for (int j = 0; j < 8; j++) {
                const int br = j * 8 + qg;
                const int bc = kk * 8 + qt;
                uint32_t b0 = f2tf(Wb[br * 36 + bc]);
                uint32_t b1 = f2tf(Wb[br * 36 + bc + 4]);
                mma_tf32(acc[0][j], a[0][0], a[0][1], a[0][2], a[0][3], b0, b1);
                mma_tf32(acc[1][j], a[1][0], a[1][1], a[1][2], a[1][3], b0, b1);
            }
        }
        __syncthreads();
    }

#pragma unroll
    for (int mt = 0; mt < 2; mt++) {
        const int row0 = m0 + wid * 32 + mt * 16 + qg;
#pragma unroll
        for (int j = 0; j < 8; j++) {
            const int col = n0 + j * 8 + 2 * qt;
            const float bz0 = bias[col], bz1 = bias[col + 1];
            float v00 = (acc[mt][j][0] + bz0) * scaleOut;
            float v01 = (acc[mt][j][1] + bz1) * scaleOut;
            float v10 = (acc[mt][j][2] + bz0) * scaleOut;
            float v11 = (acc[mt][j][3] + bz1) * scaleOut;
            if (headMajor) {
                v00 = __uint_as_float(f2tf(v00));
                v01 = __uint_as_float(f2tf(v01));
                v10 = __uint_as_float(f2tf(v10));
                v11 = __uint_as_float(f2tf(v11));
                const int h = col >> 6, d = col & 63;
                {
                    const int b = row0 >> 11, t = row0 & 2047;
                    float2 o = {v00, v01};
                    *(float2*)&out[(size_t)((b * H_ + h) * T_ + t) * D_ + d] = o;
                }
                {
                    const int r1 = row0 + 8;
                    const int b = r1 >> 11, t = r1 & 2047;
                    float2 o = {v10, v11};
                    *(float2*)&out[(size_t)((b * H_ + h) * T_ + t) * D_ + d] = o;
                }
            } else {
                float2 o0 = {v00, v01};
                float2 o1 = {v10, v11};
                *(float2*)&out[(size_t)row0 * E_ + col] = o0;
                *(float2*)&out[(size_t)(row0 + 8) * E_ + col] = o1;
            }
        }
    }
}

// ---------------------------------------------------------------------------
// Flash attention, tf32 tensor cores, S-tile = 32.
// Grid (T/128, H, B), 256 threads = 8 warps; warp owns 16 full q-rows.
// Biases (spatial+directional) stream via cp.async into a warp-private smem
// slot one tile ahead (deep MLP, no register cost). K/V double-buffered.
// ---------------------------------------------------------------------------
#define ST_ 32                            // s-tile
#define NT_ (S_/ST_)                      // 64 tiles
#define AQ_OFF  0                         // Q  [128][68]
#define AK_OFF  (128*68)                  // K  [2][32][68]
#define AKBUF   (32*68)
#define AV_OFF  (AK_OFF + 2*AKBUF)        // V  [2][32][72]
#define AVBUF   (32*72)
#define ASP_OFF (AV_OFF + 2*AVBUF)        // SP [128][36]
#define ADB_OFF (ASP_OFF + 128*36)        // DB [128][36]
#define AM_OFF  (ADB_OFF + 128*36)        // Ms [2][32]
#define ATTN_SMEM_U32 (AM_OFF + 64)
#define ATTN_SMEM_BYTES (ATTN_SMEM_U32 * 4)   // 107,776 B -> 2 CTAs/SM

__global__ void __launch_bounds__(256, 2) attn_tc(
    const float* __restrict__ spatial, const float* __restrict__ dirb,
    const float* __restrict__ amask, const unsigned char* __restrict__ pmask,
    float* __restrict__ outp)
{
    extern __shared__ uint32_t smu[];
    uint32_t* Qs  = smu + AQ_OFF;
    uint32_t* Ks  = smu + AK_OFF;
    uint32_t* Vs  = smu + AV_OFF;
    float*    SPs = (float*)(smu + ASP_OFF);
    float*    DBs = (float*)(smu + ADB_OFF);
    float*    Ms  = (float*)(smu + AM_OFF);

    const int tid  = threadIdx.x;
    const int lane = tid & 31;
    const int wid  = tid >> 5;
    const int qg   = lane >> 2;
    const int qt   = lane & 3;
    const int t0   = blockIdx.x * 128;
    const int h    = blockIdx.y;
    const int b    = blockIdx.z;
    const int r0   = wid * 16;

    const float* qbase = g_q + (size_t)((b * H_ + h) * T_ + t0) * D_;
    const float* kbase = g_k + (size_t)(b * H_ + h) * S_ * D_;
    const float* vbase = g_v + (size_t)(b * H_ + h) * S_ * D_;

    // staging roles
    const int rQ  = tid >> 1, cQ = (tid & 1) * 32;     // Q rows
    const int rKV = tid >> 3, cKV = (tid & 7) * 8;     // K/V rows (0..31)
    const int biasRow = r0 + (lane >> 1);              // warp-private bias row
    const int biasC4  = (lane & 1) * 4;                // chunk group (of 8 chunks)
    const size_t bh = (size_t)(b * H_ + h) * T_;
    const float* spRow = spatial + (bh + t0 + biasRow) * S_;
    const float* dbRow = dirb    + (bh + t0 + biasRow) * S_;
    float* spDst = SPs + biasRow * 36;
    float* dbDst = DBs + biasRow * 36;

    // ---- prologue: Q + K0/V0 + bias0 + Ms0 ----
    {
        const float* src = qbase + rQ * D_ + cQ;
        uint32_t* dst = Qs + rQ * 68 + cQ;
#pragma unroll
        for (int i = 0; i < 8; i++) cp16(dst + i * 4, src + i * 4);
        const float* ks = kbase + (size_t)rKV * D_ + cKV;
        const float* vs = vbase + (size_t)rKV * D_ + cKV;
        cp16(Ks + rKV * 68 + cKV,     ks);
        cp16(Ks + rKV * 68 + cKV + 4, ks + 4);
        cp16(Vs + rKV * 72 + cKV,     vs);
        cp16(Vs + rKV * 72 + cKV + 4, vs + 4);
#pragma unroll
        for (int t = 0; t < 4; t++) {
            const int c4 = (biasC4 + t) * 4;
            cp16(spDst + c4, spRow + c4);
            cp16(dbDst + c4, dbRow + c4);
        }
        cp_commit();
        if (tid < 32) Ms[tid] = pmask[b * S_ + tid] ? -1e30f : 0.f;
    }

    float mrow[2] = {-1e30f, -1e30f};
    float lrow[2] = {0.f, 0.f};
    float oacc[8][4];
#pragma unroll
    for (int j = 0; j < 8; j++)
#pragma unroll
        for (int i = 0; i < 4; i++) oacc[j][i] = 0.f;

    const int ra = t0 + r0 + qg;
    const int rb = ra + 8;
    const float* amA = amask + (size_t)ra * S_ + 2 * qt;
    const float* amB = amask + (size_t)rb * S_ + 2 * qt;

    const int sl1 = qt >> 1;
    const int sl2 = sl1 + 2;
    const bool oddq = qt & 1;

    for (int it = 0; it < NT_; it++) {
        const int s0  = it * ST_;
        const int cur = it & 1;
        const int nxt = cur ^ 1;

        cp_wait0();            // K/V(it) + bias(it) ready
        __syncthreads();       // single barrier per tile

        // ---- issue K/V(it+1); prefetch pmask(it+1) ----
        unsigned char pm = 0;
        if (it + 1 < NT_) {
            const int sn = s0 + ST_;
            const float* ks = kbase + (size_t)(sn + rKV) * D_ + cKV;
            const float* vs = vbase + (size_t)(sn + rKV) * D_ + cKV;
            cp16(Ks + nxt * AKBUF + rKV * 68 + cKV,     ks);
            cp16(Ks + nxt * AKBUF + rKV * 68 + cKV + 4, ks + 4);
            cp16(Vs + nxt * AVBUF + rKV * 72 + cKV,     vs);
            cp16(Vs + nxt * AVBUF + rKV * 72 + cKV + 4, vs + 4);
            cp_commit();
            if (tid < 32) pm = pmask[b * S_ + sn + tid];
        }

        // ---- hoisted amask loads (L2-resident) ----
        float2 am1[4], am2[4];
#pragma unroll
        for (int j = 0; j < 4; j++) {
            am1[j] = *(const float2*)(amA + s0 + j * 8);
            am2[j] = *(const float2*)(amB + s0 + j * 8);
        }

        // ---- QK^T: S[16 x 32] per warp ----
        const uint32_t* Kc = Ks + cur * AKBUF;
        float sacc[4][4];
#pragma unroll
        for (int j = 0; j < 4; j++)
#pragma unroll
            for (int i = 0; i < 4; i++) sacc[j][i] = 0.f;

#pragma unroll
        for (int kk = 0; kk < 8; kk++) {
            const int ar = r0 + qg, ac = kk * 8 + qt;
            uint32_t a0 = Qs[ar * 68 + ac];
            uint32_t a1 = Qs[(ar + 8) * 68 + ac];
            uint32_t a2 = Qs[ar * 68 + ac + 4];
            uint32_t a3 = Qs[(ar + 8) * 68 + ac + 4];
#pragma unroll
            for (int j = 0; j < 4; j++) {
                const int br = j * 8 + qg;
                uint32_t b0 = Kc[br * 68 + ac];
                uint32_t b1 = Kc[br * 68 + ac + 4];
                mma_tf32(sacc[j], a0, a1, a2, a3, b0, b1);
            }
        }

        // ---- add biases (from smem) + amask + pad mask ----
        const float* SPr0 = SPs + (r0 + qg) * 36;
        const float* SPr8 = SPs + (r0 + qg + 8) * 36;
        const float* DBr0 = DBs + (r0 + qg) * 36;
        const float* DBr8 = DBs + (r0 + qg + 8) * 36;
#pragma unroll
        for (int j = 0; j < 4; j++) {
            const int c = j * 8 + 2 * qt;
            float2 sp1 = *(const float2*)(SPr0 + c);
            float2 sp2 = *(const float2*)(SPr8 + c);
            float2 db1 = *(const float2*)(DBr0 + c);
            float2 db2 = *(const float2*)(DBr8 + c);
            const float mk0 = Ms[cur * 32 + c], mk1 = Ms[cur * 32 + c + 1];
            sacc[j][0] = sacc[j][0] + am1[j].x + sp1.x + db1.x + mk0;
            sacc[j][1] = sacc[j][1] + am1[j].y + sp1.y + db1.y + mk1;
            sacc[j][2] = sacc[j][2] + am2[j].x + sp2.x + db2.x + mk0;
            sacc[j][3] = sacc[j][3] + am2[j].y + sp2.y + db2.y + mk1;
        }

        // ---- issue bias(it+1) into the (now consumed, warp-private) slot ----
        if (it + 1 < NT_) {
            const int sn = s0 + ST_;
#pragma unroll
            for (int t = 0; t < 4; t++) {
                const int c4 = (biasC4 + t) * 4;
                cp16(spDst + c4, spRow + sn + c4);
                cp16(dbDst + c4, dbRow + sn + c4);
            }
            cp_commit();
        }

        // ---- online softmax ----
        float mx0 = mrow[0], mx1 = mrow[1];
#pragma unroll
        for (int j = 0; j < 4; j++) {
            mx0 = fmaxf(mx0, fmaxf(sacc[j][0], sacc[j][1]));
            mx1 = fmaxf(mx1, fmaxf(sacc[j][2], sacc[j][3]));
        }
        mx0 = fmaxf(mx0, __shfl_xor_sync(0xFFFFFFFFu, mx0, 1));
        mx0 = fmaxf(mx0, __shfl_xor_sync(0xFFFFFFFFu, mx0, 2));
        mx1 = fmaxf(mx1, __shfl_xor_sync(0xFFFFFFFFu, mx1, 1));
        mx1 = fmaxf(mx1, __shfl_xor_sync(0xFFFFFFFFu, mx1, 2));

        const float al0 = __expf(mrow[0] - mx0);
        const float al1 = __expf(mrow[1] - mx1);
        float ls0 = 0.f, ls1 = 0.f;
#pragma unroll
        for (int j = 0; j < 4; j++) {
            sacc[j][0] = __expf(sacc[j][0] - mx0);
            sacc[j][1] = __expf(sacc[j][1] - mx0);
            sacc[j][2] = __expf(sacc[j][2] - mx1);
            sacc[j][3] = __expf(sacc[j][3] - mx1);
            ls0 += sacc[j][0] + sacc[j][1];
            ls1 += sacc[j][2] + sacc[j][3];
        }
        ls0 += __shfl_xor_sync(0xFFFFFFFFu, ls0, 1);
        ls0 += __shfl_xor_sync(0xFFFFFFFFu, ls0, 2);
        ls1 += __shfl_xor_sync(0xFFFFFFFFu, ls1, 1);
        ls1 += __shfl_xor_sync(0xFFFFFFFFu, ls1, 2);
        mrow[0] = mx0; mrow[1] = mx1;
        lrow[0] = lrow[0] * al0 + ls0;
        lrow[1] = lrow[1] * al1 + ls1;
#pragma unroll
        for (int j = 0; j < 8; j++) {
            oacc[j][0] *= al0; oacc[j][1] *= al0;
            oacc[j][2] *= al1; oacc[j][3] *= al1;
        }

        // ---- PV: quad-shuffle transpose of P fragments, then MMA ----
        const uint32_t* Vc = Vs + cur * AVBUF;
#pragma unroll
        for (int kk = 0; kk < 4; kk++) {
            uint32_t x0 = f2tf(sacc[kk][0]);
            uint32_t x1 = f2tf(sacc[kk][1]);
            uint32_t x2 = f2tf(sacc[kk][2]);
            uint32_t x3 = f2tf(sacc[kk][3]);
            uint32_t t00 = __shfl_sync(0xFFFFFFFFu, x0, sl1, 4);
            uint32_t t01 = __shfl_sync(0xFFFFFFFFu, x1, sl1, 4);
            uint32_t t02 = __shfl_sync(0xFFFFFFFFu, x2, sl1, 4);
            uint32_t t03 = __shfl_sync(0xFFFFFFFFu, x3, sl1, 4);
            uint32_t t10 = __shfl_sync(0xFFFFFFFFu, x0, sl2, 4);
            uint32_t t11 = __shfl_sync(0xFFFFFFFFu, x1, sl2, 4);
            uint32_t t12 = __shfl_sync(0xFFFFFFFFu, x2, sl2, 4);
            uint32_t t13 = __shfl_sync(0xFFFFFFFFu, x3, sl2, 4);
            uint32_t a0 = oddq ? t01 : t00;
            uint32_t a1 = oddq ? t03 : t02;
            uint32_t a2 = oddq ? t11 : t10;
            uint32_t a3 = oddq ? t13 : t12;
            const int br = kk * 8 + qt;
#pragma unroll
            for (int j = 0; j < 8; j++) {
                const int bc = j * 8 + qg;
                uint32_t b0 = Vc[br * 72 + bc];
                uint32_t b1 = Vc[(br + 4) * 72 + bc];
                mma_tf32(oacc[j], a0, a1, a2, a3, b0, b1);
            }
        }

        // ---- store pad mask for next tile ----
        if (it + 1 < NT_ && tid < 32)
            Ms[nxt * 32 + tid] = pm ? -1e30f : 0.f;
    }

    // ---- epilogue ----
    const float inv0 = 1.f / lrow[0];
    const float inv1 = 1.f / lrow[1];
    float* oA = outp + (size_t)(b * T_ + ra) * E_ + h * D_;
    float* oB = outp + (size_t)(b * T_ + rb) * E_ + h * D_;
#pragma unroll
    for (int j = 0; j < 8; j++) {
        const int c = j * 8 + 2 * qt;
        float2 o0 = {oacc[j][0] * inv0, oacc[j][1] * inv0};
        float2 o1 = {oacc[j][2] * inv1, oacc[j][3] * inv1};
        *(float2*)(oA + c) = o0;
        *(float2*)(oB + c) = o1;
    }
}

// ---------------------------------------------------------------------------
extern "C" void kernel_launch(void* const* d_in, const int* in_sizes, int n_in,
                              void* d_out, int out_size)
{
    const float* query = (const float*)d_in[0];
    const float* key   = (const float*)d_in[1];
    const float* value = (const float*)d_in[2];
    const float* spatial = (const float*)d_in[3];
    const float* dirb    = (const float*)d_in[4];
    const unsigned char* pmask = (const unsigned char*)d_in[5];
    const float* amask = (const float*)d_in[6];
    const float* Wq = (const float*)d_in[7];
    const float* bq = (const float*)d_in[8];
    const float* Wk = (const float*)d_in[9];
    const float* bk = (const float*)d_in[10];
    const float* Wv = (const float*)d_in[11];
    const float* bv = (const float*)d_in[12];
    const float* Wo = (const float*)d_in[13];
    const float* bo = (const float*)d_in[14];
    float* out = (float*)d_out;

    float *qp, *kp, *vp, *ap;
    cudaGetSymbolAddress((void**)&qp, g_q);
    cudaGetSymbolAddress((void**)&kp, g_k);
    cudaGetSymbolAddress((void**)&vp, g_v);
    cudaGetSymbolAddress((void**)&ap, g_attn);

    cudaFuncSetAttribute(gemm_tc,
                         cudaFuncAttributeMaxDynamicSharedMemorySize,
                         GEMM_SMEM_BYTES);
    cudaFuncSetAttribute(attn_tc,
                         cudaFuncAttributeMaxDynamicSharedMemorySize,
                         ATTN_SMEM_BYTES);

    const dim3 gb(E_ / 64, M_ / 256);   // (16, 16)
    gemm_tc<<<gb, 256, GEMM_SMEM_BYTES>>>(query, Wq, bq, qp, 1, 0.125f);
    gemm_tc<<<gb, 256, GEMM_SMEM_BYTES>>>(key,   Wk, bk, kp, 1, 1.0f);
    gemm_tc<<<gb, 256, GEMM_SMEM_BYTES>>>(value, Wv, bv, vp, 1, 1.0f);

    attn_tc<<<dim3(T_ / 128, H_, B_), 256, ATTN_SMEM_BYTES>>>(
        spatial, dirb, amask, pmask, ap);

    gemm_tc<<<gb, 256, GEMM_SMEM_BYTES>>>(ap, Wo, bo, out, 0, 1.0f);
}